// round 9
// baseline (speedup 1.0000x reference)
#include <cuda_runtime.h>
#include <cuda_bf16.h>
#include <cuda_fp16.h>
#include <cstdint>

// Problem constants
#define BB 4
#define NN 10000
#define EE 170000
#define F_IN 256
#define FF 128
#define HH 4
#define MROWS (BB * NN)             // 40000
#define CCOLS (HH * FF)             // 512
#define NODE_STRIDE (BB * HH * FF)  // 2048 elements per node
#define BM 256
#define MTILES 157                  // ceil(40000/256)
#define MPAD (MTILES * BM)          // 40192

// Scratch (device globals; no allocation allowed)
__device__ __align__(16) __half g_h16[(size_t)NN * NODE_STRIDE];  // fp16 h (41MB)
__device__ float g_ps[HH * NN];
__device__ float g_pd[HH * NN];
__device__ __align__(16) float g_wa[8 * F_IN];   // [src h0-3 | dst h0-3][k]
__device__ float g_wac[8];                        // bias dot a
// bf16 split images, row-major
__device__ __align__(16) __nv_bfloat16 g_Ahi[(size_t)MPAD * F_IN];
__device__ __align__(16) __nv_bfloat16 g_Alo[(size_t)MPAD * F_IN];
__device__ __align__(16) __nv_bfloat16 g_Bhi[HH * FF * F_IN];   // [head][f][k]
__device__ __align__(16) __nv_bfloat16 g_Blo[HH * FF * F_IN];

static __device__ __forceinline__ uint32_t smem_u32(const void* p) {
    uint32_t a;
    asm("{ .reg .u64 t; cvta.to.shared.u64 t, %1; cvt.u32.u64 %0, t; }" : "=r"(a) : "l"(p));
    return a;
}
static __device__ __forceinline__ void cp16(uint32_t dst, const void* src) {
    asm volatile("cp.async.cg.shared.global [%0], [%1], 16;" :: "r"(dst), "l"(src));
}
static __device__ __forceinline__ void ldm_x4(uint32_t& r0, uint32_t& r1, uint32_t& r2,
                                              uint32_t& r3, uint32_t addr) {
    asm volatile("ldmatrix.sync.aligned.m8n8.x4.shared.b16 {%0,%1,%2,%3}, [%4];"
                 : "=r"(r0), "=r"(r1), "=r"(r2), "=r"(r3) : "r"(addr));
}
static __device__ __forceinline__ void mma_bf16(float* c, const uint32_t* a, const uint32_t* b) {
    asm volatile(
        "mma.sync.aligned.m16n8k16.row.col.f32.bf16.bf16.f32 "
        "{%0,%1,%2,%3}, {%4,%5,%6,%7}, {%8,%9}, {%0,%1,%2,%3};"
        : "+f"(c[0]), "+f"(c[1]), "+f"(c[2]), "+f"(c[3])
        : "r"(a[0]), "r"(a[1]), "r"(a[2]), "r"(a[3]), "r"(b[0]), "r"(b[1]));
}

// ---------------------------------------------------------------------------
// Prep 0: Wa[vec][k] = sum_f W_mlp[h][k][f] * a_vec[h][f];  wac[vec] = b.a
// vec = which*4 + h, which: 0=src (a = Wattn[h][0:128]), 1=dst (128:256)
// ---------------------------------------------------------------------------
__global__ __launch_bounds__(128) void prep_wa(const float* __restrict__ W,
                                               const float* __restrict__ bias,
                                               const float* __restrict__ Wattn)
{
    const int vec = blockIdx.x;          // 0..7
    const int h = vec & 3;
    const int which = vec >> 2;
    const float* a = Wattn + h * (2 * FF) + which * FF;

    for (int k = threadIdx.x; k < F_IN; k += 128) {
        const float* wr = W + (size_t)h * F_IN * FF + (size_t)k * FF;
        float s = 0.f;
        #pragma unroll 4
        for (int f = 0; f < FF; f++) s = fmaf(wr[f], a[f], s);
        g_wa[vec * F_IN + k] = s;
    }
    if (threadIdx.x == 0) {
        float c = 0.f;
        for (int f = 0; f < FF; f++) c = fmaf(bias[h * FF + f], a[f], c);
        g_wac[vec] = c;
    }
}

// ---------------------------------------------------------------------------
// Prep 1: split x into bf16 hi/lo (pad m to MPAD). Fused: for batch B-1 rows,
// compute p_src/p_dst = x_row . Wa_vec + wac_vec  (warp == one m row).
// ---------------------------------------------------------------------------
__global__ __launch_bounds__(256) void prep_x(const float* __restrict__ x)
{
    int idx = blockIdx.x * 256 + threadIdx.x;      // m*32 + kgroup
    if (idx >= MPAD * 32) return;
    int m    = idx >> 5;
    int lane = idx & 31;
    int kg   = lane << 3;

    float v[8];
    if (m < MROWS) {
        const float4* p = (const float4*)(x + (size_t)m * F_IN + kg);
        float4 a = p[0], b = p[1];
        v[0] = a.x; v[1] = a.y; v[2] = a.z; v[3] = a.w;
        v[4] = b.x; v[5] = b.y; v[6] = b.z; v[7] = b.w;
    } else {
        #pragma unroll
        for (int j = 0; j < 8; j++) v[j] = 0.f;
    }
    __nv_bfloat16 h8[8], l8[8];
    #pragma unroll
    for (int j = 0; j < 8; j++) {
        __nv_bfloat16 h = __float2bfloat16(v[j]);
        h8[j] = h;
        l8[j] = __float2bfloat16(v[j] - __bfloat162float(h));
    }
    *(uint4*)(g_Ahi + (size_t)m * F_IN + kg) = *(const uint4*)h8;
    *(uint4*)(g_Alo + (size_t)m * F_IN + kg) = *(const uint4*)l8;

    // fused pvec for batch B-1 (warp-uniform branch: warp == one m)
    if (m >= (BB - 1) * NN && m < BB * NN) {
        float part[8];
        #pragma unroll
        for (int vec = 0; vec < 8; vec++) {
            const float* wa = g_wa + vec * F_IN + kg;
            float s = 0.f;
            #pragma unroll
            for (int j = 0; j < 8; j++) s = fmaf(v[j], wa[j], s);
            part[vec] = s;
        }
        #pragma unroll
        for (int o = 16; o > 0; o >>= 1)
            #pragma unroll
            for (int vec = 0; vec < 8; vec++)
                part[vec] += __shfl_down_sync(0xffffffffu, part[vec], o);
        if (lane == 0) {
            int n = m - (BB - 1) * NN;
            #pragma unroll
            for (int h = 0; h < 4; h++) {
                g_ps[h * NN + n] = part[h] + g_wac[h];
                g_pd[h * NN + n] = part[4 + h] + g_wac[4 + h];
            }
        }
    }
}

// ---------------------------------------------------------------------------
// Prep 2: Bt[head][f][k] = W_mlp[head][k][f], bf16 hi/lo.
// ---------------------------------------------------------------------------
__global__ __launch_bounds__(256) void prep_w(const float* __restrict__ W)
{
    int idx = blockIdx.x * 256 + threadIdx.x;      // head*4096 + f*32 + kgroup
    if (idx >= HH * FF * 32) return;
    int head = idx >> 12;
    int f    = (idx >> 5) & 127;
    int kg   = (idx & 31) << 3;

    __nv_bfloat16 h8[8], l8[8];
    #pragma unroll
    for (int j = 0; j < 8; j++) {
        float v = W[(size_t)head * F_IN * FF + (size_t)(kg + j) * FF + f];
        __nv_bfloat16 h = __float2bfloat16(v);
        h8[j] = h;
        l8[j] = __float2bfloat16(v - __bfloat162float(h));
    }
    size_t o = ((size_t)head * FF + f) * F_IN + kg;
    *(uint4*)(g_Bhi + o) = *(const uint4*)h8;
    *(uint4*)(g_Blo + o) = *(const uint4*)l8;
}

// ---------------------------------------------------------------------------
// Tensor-core GEMM via mma.sync (bf16, fp32 accum), split-bf16 3-pass.
// grid = (4 heads fastest, 157 m-tiles). CTA 256m x 128n, BK=64,
// double-buffered cp.async (192KB smem). 8 warps = 4(m) x 2(n); warp 64x64.
// ---------------------------------------------------------------------------
#define BK 64
#define A_SUB 32768                // 256 rows * 128 B
#define B_SUB 16384                // 128 rows * 128 B
#define STAGE_BYTES 98304          // 2*A_SUB + 2*B_SUB
#define GEMM_SMEM (2 * STAGE_BYTES)

static __device__ __forceinline__ uint32_t sw_off(int row, int chunk) {
    return (uint32_t)(row * 128 + ((chunk ^ (row & 7)) << 4));
}

__global__ __launch_bounds__(256, 1) void gemm_mma(const float* __restrict__ bias)
{
    extern __shared__ __align__(16) unsigned char smem[];
    const uint32_t sb = smem_u32(smem);
    const int tid  = threadIdx.x;
    const int wid  = tid >> 5;
    const int lane = tid & 31;
    const int head = blockIdx.x;
    const int tile = blockIdx.y;

    const __nv_bfloat16* gA[2];
    const __nv_bfloat16* gB[2];
    gA[0] = g_Ahi + (size_t)tile * BM * F_IN;
    gA[1] = g_Alo + (size_t)tile * BM * F_IN;
    gB[0] = g_Bhi + (size_t)head * FF * F_IN;
    gB[1] = g_Blo + (size_t)head * FF * F_IN;

    const int mw = wid & 3;        // m block (64 rows)
    const int nw = wid >> 2;       // n block (64 cols)

    float acc[4][8][4];
    #pragma unroll
    for (int i = 0; i < 4; i++)
        #pragma unroll
        for (int j = 0; j < 8; j++)
            #pragma unroll
            for (int q = 0; q < 4; q++) acc[i][j][q] = 0.f;

    auto prefetch = [&](int stage, int kc0) {
        uint32_t sdst = sb + stage * STAGE_BYTES;
        #pragma unroll
        for (int sub = 0; sub < 2; sub++) {
            #pragma unroll
            for (int i = 0; i < 8; i++) {
                int idx = tid + i * 256;            // 0..2047
                int row = idx >> 3;
                int ch  = idx & 7;
                cp16(sdst + sub * A_SUB + sw_off(row, ch),
                     gA[sub] + (size_t)row * F_IN + kc0 + ch * 8);
            }
        }
        #pragma unroll
        for (int sub = 0; sub < 2; sub++) {
            #pragma unroll
            for (int i = 0; i < 4; i++) {
                int idx = tid + i * 256;            // 0..1023
                int row = idx >> 3;
                int ch  = idx & 7;
                cp16(sdst + 2 * A_SUB + sub * B_SUB + sw_off(row, ch),
                     gB[sub] + (size_t)row * F_IN + kc0 + ch * 8);
            }
        }
        asm volatile("cp.async.commit_group;" ::: "memory");
    };

    prefetch(0, 0);

    for (int c = 0; c < 4; c++) {
        if (c + 1 < 4) {
            prefetch((c + 1) & 1, (c + 1) * BK);
            asm volatile("cp.async.wait_group 1;" ::: "memory");
        } else {
            asm volatile("cp.async.wait_group 0;" ::: "memory");
        }
        __syncthreads();

        const uint32_t stb = sb + (c & 1) * STAGE_BYTES;
        const int a_row = mw * 64 + (lane & 7) + ((lane >> 3 & 1) << 3);
        const int a_chx = lane >> 4;
        const int b_row = nw * 64 + (lane & 7) + ((lane >> 4) << 3);
        const int b_chx = (lane >> 3) & 1;

        #pragma unroll
        for (int p = 0; p < 3; p++) {
            const uint32_t abase = stb + ((p == 2) ? A_SUB : 0);
            const uint32_t bbase = stb + 2 * A_SUB + ((p == 1) ? B_SUB : 0);
            #pragma unroll
            for (int ks = 0; ks < 4; ks++) {
                const int c0 = ks * 2;
                uint32_t a[4][4];
                #pragma unroll
                for (int mi = 0; mi < 4; mi++)
                    ldm_x4(a[mi][0], a[mi][1], a[mi][2], a[mi][3],
                           abase + sw_off(a_row + mi * 16, c0 + a_chx));
                uint32_t b[8][2];
                #pragma unroll
                for (int j = 0; j < 4; j++) {
                    uint32_t r0, r1, r2, r3;
                    ldm_x4(r0, r1, r2, r3,
                           bbase + sw_off(b_row + j * 16, c0 + b_chx));
                    b[2 * j][0] = r0; b[2 * j][1] = r1;
                    b[2 * j + 1][0] = r2; b[2 * j + 1][1] = r3;
                }
                #pragma unroll
                for (int mi = 0; mi < 4; mi++)
                    #pragma unroll
                    for (int ni = 0; ni < 8; ni++)
                        mma_bf16(acc[mi][ni], a[mi], b[ni]);
            }
        }
        __syncthreads();
    }

    // Epilogue: add bias; write fp16 h
    const int col0 = nw * 64 + 2 * (lane & 3);
    #pragma unroll
    for (int mi = 0; mi < 4; mi++) {
        const int rl = mw * 64 + mi * 16 + (lane >> 2);
        #pragma unroll
        for (int half = 0; half < 2; half++) {
            const int m = tile * BM + rl + half * 8;
            if (m >= MROWS) continue;
            const int bidx = m / NN;
            const int n = m - bidx * NN;
            __half* op16 = g_h16 + (size_t)n * NODE_STRIDE + bidx * (HH * FF) + head * FF;
            #pragma unroll
            for (int ni = 0; ni < 8; ni++) {
                const int col = col0 + ni * 8;
                float ox = acc[mi][ni][half * 2 + 0] + bias[head * FF + col];
                float oy = acc[mi][ni][half * 2 + 1] + bias[head * FF + col + 1];
                *(__half2*)(op16 + col) = __floats2half2_rn(ox, oy);
            }
        }
    }
}

// ---------------------------------------------------------------------------
// Aggregation (one block per src node). Fused row-range binary search.
// ---------------------------------------------------------------------------
#define ACHUNK 128
__global__ __launch_bounds__(256) void agg_kernel(
    const int* __restrict__ src,
    const int* __restrict__ dst,
    float* __restrict__ out)
{
    const int n = blockIdx.x;
    const int t = threadIdx.x;

    __shared__ int   s_e01[2];
    __shared__ int   s_dst[ACHUNK];
    __shared__ float s_w[HH][ACHUNK];
    __shared__ float s_den[HH];

    if (t == 0 || t == 32) {
        int key = n + (t >> 5);
        int lo = 0, hi = EE;
        while (lo < hi) {
            int mid = (lo + hi) >> 1;
            if (src[mid] < key) lo = mid + 1; else hi = mid;
        }
        s_e01[t >> 5] = lo;
    }
    __syncthreads();
    const int e0 = s_e01[0];
    const int e1 = s_e01[1];

    const int base = t * 8;              // 2048 elems = 256 threads * 8
    const int hi = (base >> 7) & 3;
    const int b  = base >> 9;

    float acc[8];
    #pragma unroll
    for (int j = 0; j < 8; j++) acc[j] = 0.f;
    float den_local = 0.f;

    for (int cs = e0; cs < e1; cs += ACHUNK) {
        const int m = min(cs + ACHUNK, e1) - cs;
        if (t < m) {
            int e = cs + t;
            int d = dst[e];
            s_dst[t] = d;
            #pragma unroll
            for (int h = 0; h < HH; h++) {
                float s = g_ps[h * NN + n] + g_pd[h * NN + d];
                s = (s >= 0.f) ? s : 0.2f * s;
                s = fminf(fmaxf(s, -2.f), 2.f);
                s_w[h][t] = __expf(s);
            }
        }
        __syncthreads();

        if (t < HH) {
            float sm = 0.f;
            for (int e = 0; e < m; e++) sm += s_w[t][e];
            den_local += sm;
        }

        #pragma unroll 2
        for (int e = 0; e < m; e++) {
            float w = s_w[hi][e];
            uint4 v = *(const uint4*)(g_h16 + (size_t)s_dst[e] * NODE_STRIDE + base);
            float2 f0 = __half22float2(*reinterpret_cast<__half2*>(&v.x));
            float2 f1 = __half22float2(*reinterpret_cast<__half2*>(&v.y));
            float2 f2 = __half22float2(*reinterpret_cast<__half2*>(&v.z));
            float2 f3 = __half22float2(*reinterpret_cast<__half2*>(&v.w));
            acc[0] = fmaf(w, f0.x, acc[0]);
            acc[1] = fmaf(w, f0.y, acc[1]);
            acc[2] = fmaf(w, f1.x, acc[2]);
            acc[3] = fmaf(w, f1.y, acc[3]);
            acc[4] = fmaf(w, f2.x, acc[4]);
            acc[5] = fmaf(w, f2.y, acc[5]);
            acc[6] = fmaf(w, f3.x, acc[6]);
            acc[7] = fmaf(w, f3.y, acc[7]);
        }
        __syncthreads();
    }

    if (t < HH) s_den[t] = den_local;
    __syncthreads();

    float inv = (e1 > e0) ? (1.f / s_den[hi]) : 0.f;
    float* op = out + ((size_t)b * NN + n) * CCOLS + (base & (CCOLS - 1));
    float4 o0, o1;
    o0.x = acc[0] * inv; o0.y = acc[1] * inv; o0.z = acc[2] * inv; o0.w = acc[3] * inv;
    o1.x = acc[4] * inv; o1.y = acc[5] * inv; o1.z = acc[6] * inv; o1.w = acc[7] * inv;
    ((float4*)op)[0] = o0;
    ((float4*)op)[1] = o1;
}

// ---------------------------------------------------------------------------
// Launch
// ---------------------------------------------------------------------------
extern "C" void kernel_launch(void* const* d_in, const int* in_sizes, int n_in,
                              void* d_out, int out_size)
{
    const float* x     = (const float*)d_in[0];
    const float* Wmlp  = (const float*)d_in[1];
    const float* bmlp  = (const float*)d_in[2];
    const float* Wattn = (const float*)d_in[3];
    const int*   src   = (const int*)d_in[4];
    const int*   dst   = (const int*)d_in[5];
    float*       out   = (float*)d_out;

    (void)in_sizes; (void)n_in; (void)out_size;

    cudaFuncSetAttribute(gemm_mma, cudaFuncAttributeMaxDynamicSharedMemorySize, GEMM_SMEM);

    prep_wa<<<8, 128>>>(Wmlp, bmlp, Wattn);
    prep_w<<<(HH * FF * 32 + 255) / 256, 256>>>(Wmlp);
    prep_x<<<(MPAD * 32 + 255) / 256, 256>>>(x);

    gemm_mma<<<dim3(HH, MTILES), 256, GEMM_SMEM>>>(bmlp);

    agg_kernel<<<NN, 256>>>(src, dst, out);
}

// round 10
// speedup vs baseline: 1.0434x; 1.0434x over previous
#include <cuda_runtime.h>
#include <cuda_bf16.h>
#include <cuda_fp16.h>
#include <cstdint>

// Problem constants
#define BB 4
#define NN 10000
#define EE 170000
#define F_IN 256
#define FF 128
#define HH 4
#define MROWS (BB * NN)             // 40000
#define CCOLS (HH * FF)             // 512
#define NODE_STRIDE (BB * HH * FF)  // 2048 elements per node
#define BM 128
#define MTILES 313                  // ceil(40000/128)
#define MPAD (MTILES * BM)          // 40064

// Scratch (device globals; no allocation allowed)
__device__ __align__(16) __half g_h16[(size_t)NN * NODE_STRIDE];  // fp16 h (41MB)
__device__ float g_ps[HH * NN];
__device__ float g_pd[HH * NN];
__device__ __align__(16) float g_wa[8 * F_IN];   // [src h0-3 | dst h0-3][k]
__device__ float g_wac[8];                        // bias dot a
// bf16 split images, row-major
__device__ __align__(16) __nv_bfloat16 g_Ahi[(size_t)MPAD * F_IN];
__device__ __align__(16) __nv_bfloat16 g_Alo[(size_t)MPAD * F_IN];
__device__ __align__(16) __nv_bfloat16 g_Bhi[HH * FF * F_IN];   // [head][f][k]
__device__ __align__(16) __nv_bfloat16 g_Blo[HH * FF * F_IN];

static __device__ __forceinline__ uint32_t smem_u32(const void* p) {
    uint32_t a;
    asm("{ .reg .u64 t; cvta.to.shared.u64 t, %1; cvt.u32.u64 %0, t; }" : "=r"(a) : "l"(p));
    return a;
}
static __device__ __forceinline__ void cp16(uint32_t dst, const void* src) {
    asm volatile("cp.async.cg.shared.global [%0], [%1], 16;" :: "r"(dst), "l"(src));
}
static __device__ __forceinline__ void ldm_x4(uint32_t& r0, uint32_t& r1, uint32_t& r2,
                                              uint32_t& r3, uint32_t addr) {
    asm volatile("ldmatrix.sync.aligned.m8n8.x4.shared.b16 {%0,%1,%2,%3}, [%4];"
                 : "=r"(r0), "=r"(r1), "=r"(r2), "=r"(r3) : "r"(addr));
}
static __device__ __forceinline__ void mma_bf16(float* c, const uint32_t* a, const uint32_t* b) {
    asm volatile(
        "mma.sync.aligned.m16n8k16.row.col.f32.bf16.bf16.f32 "
        "{%0,%1,%2,%3}, {%4,%5,%6,%7}, {%8,%9}, {%0,%1,%2,%3};"
        : "+f"(c[0]), "+f"(c[1]), "+f"(c[2]), "+f"(c[3])
        : "r"(a[0]), "r"(a[1]), "r"(a[2]), "r"(a[3]), "r"(b[0]), "r"(b[1]));
}

// ---------------------------------------------------------------------------
// Prep 0: Wa[vec][k] = sum_f W_mlp[h][k][f] * a_vec[h][f];  wac[vec] = b.a
// ---------------------------------------------------------------------------
__global__ __launch_bounds__(128) void prep_wa(const float* __restrict__ W,
                                               const float* __restrict__ bias,
                                               const float* __restrict__ Wattn)
{
    const int vec = blockIdx.x;          // 0..7
    const int h = vec & 3;
    const int which = vec >> 2;
    const float* a = Wattn + h * (2 * FF) + which * FF;

    for (int k = threadIdx.x; k < F_IN; k += 128) {
        const float* wr = W + (size_t)h * F_IN * FF + (size_t)k * FF;
        float s = 0.f;
        #pragma unroll 4
        for (int f = 0; f < FF; f++) s = fmaf(wr[f], a[f], s);
        g_wa[vec * F_IN + k] = s;
    }
    if (threadIdx.x == 0) {
        float c = 0.f;
        for (int f = 0; f < FF; f++) c = fmaf(bias[h * FF + f], a[f], c);
        g_wac[vec] = c;
    }
}

// ---------------------------------------------------------------------------
// Prep 1: split x into bf16 hi/lo (pad to MPAD). Fused pvec for batch B-1.
// ---------------------------------------------------------------------------
__global__ __launch_bounds__(256) void prep_x(const float* __restrict__ x)
{
    int idx = blockIdx.x * 256 + threadIdx.x;      // m*32 + kgroup
    if (idx >= MPAD * 32) return;
    int m    = idx >> 5;
    int lane = idx & 31;
    int kg   = lane << 3;

    float v[8];
    if (m < MROWS) {
        const float4* p = (const float4*)(x + (size_t)m * F_IN + kg);
        float4 a = p[0], b = p[1];
        v[0] = a.x; v[1] = a.y; v[2] = a.z; v[3] = a.w;
        v[4] = b.x; v[5] = b.y; v[6] = b.z; v[7] = b.w;
    } else {
        #pragma unroll
        for (int j = 0; j < 8; j++) v[j] = 0.f;
    }
    __nv_bfloat16 h8[8], l8[8];
    #pragma unroll
    for (int j = 0; j < 8; j++) {
        __nv_bfloat16 h = __float2bfloat16(v[j]);
        h8[j] = h;
        l8[j] = __float2bfloat16(v[j] - __bfloat162float(h));
    }
    *(uint4*)(g_Ahi + (size_t)m * F_IN + kg) = *(const uint4*)h8;
    *(uint4*)(g_Alo + (size_t)m * F_IN + kg) = *(const uint4*)l8;

    if (m >= (BB - 1) * NN && m < BB * NN) {
        float part[8];
        #pragma unroll
        for (int vec = 0; vec < 8; vec++) {
            const float* wa = g_wa + vec * F_IN + kg;
            float s = 0.f;
            #pragma unroll
            for (int j = 0; j < 8; j++) s = fmaf(v[j], wa[j], s);
            part[vec] = s;
        }
        #pragma unroll
        for (int o = 16; o > 0; o >>= 1)
            #pragma unroll
            for (int vec = 0; vec < 8; vec++)
                part[vec] += __shfl_down_sync(0xffffffffu, part[vec], o);
        if (lane == 0) {
            int n = m - (BB - 1) * NN;
            #pragma unroll
            for (int h = 0; h < 4; h++) {
                g_ps[h * NN + n] = part[h] + g_wac[h];
                g_pd[h * NN + n] = part[4 + h] + g_wac[4 + h];
            }
        }
    }
}

// ---------------------------------------------------------------------------
// Prep 2: Bt[head][f][k] = W_mlp[head][k][f], bf16 hi/lo.
// ---------------------------------------------------------------------------
__global__ __launch_bounds__(256) void prep_w(const float* __restrict__ W)
{
    int idx = blockIdx.x * 256 + threadIdx.x;      // head*4096 + f*32 + kgroup
    if (idx >= HH * FF * 32) return;
    int head = idx >> 12;
    int f    = (idx >> 5) & 127;
    int kg   = (idx & 31) << 3;

    __nv_bfloat16 h8[8], l8[8];
    #pragma unroll
    for (int j = 0; j < 8; j++) {
        float v = W[(size_t)head * F_IN * FF + (size_t)(kg + j) * FF + f];
        __nv_bfloat16 h = __float2bfloat16(v);
        h8[j] = h;
        l8[j] = __float2bfloat16(v - __bfloat162float(h));
    }
    size_t o = ((size_t)head * FF + f) * F_IN + kg;
    *(uint4*)(g_Bhi + o) = *(const uint4*)h8;
    *(uint4*)(g_Blo + o) = *(const uint4*)l8;
}

// ---------------------------------------------------------------------------
// Tensor-core GEMM, split-bf16 3-pass. CTA 128m x 128n, BK=32, 3-stage
// cp.async pipeline. Stage row = 128B: hi in 16B-chunks 0-3, lo in 4-7
// (same 8-chunk XOR swizzle as before). smem 96KB -> 2 CTAs/SM,
// launch_bounds(256,2) caps regs at 128. 8 warps = 4m x 2n, warp 32x64.
// ---------------------------------------------------------------------------
#define BK 32
#define NSTAGE 3
#define A_SUB 16384                // 128 rows * 128B (hi+lo packed)
#define STAGE_BYTES 32768          // A_SUB + B_SUB
#define GEMM_SMEM (NSTAGE * STAGE_BYTES)

static __device__ __forceinline__ uint32_t sw_off(int row, int chunk) {
    return (uint32_t)(row * 128 + ((chunk ^ (row & 7)) << 4));
}

__global__ __launch_bounds__(256, 2) void gemm_mma(const float* __restrict__ bias)
{
    extern __shared__ __align__(16) unsigned char smem[];
    const uint32_t sb = smem_u32(smem);
    const int tid  = threadIdx.x;
    const int wid  = tid >> 5;
    const int lane = tid & 31;
    const int head = blockIdx.x;
    const int tile = blockIdx.y;

    const __nv_bfloat16* gA[2];
    const __nv_bfloat16* gB[2];
    gA[0] = g_Ahi + (size_t)tile * BM * F_IN;
    gA[1] = g_Alo + (size_t)tile * BM * F_IN;
    gB[0] = g_Bhi + (size_t)head * FF * F_IN;
    gB[1] = g_Blo + (size_t)head * FF * F_IN;

    const int mw = wid & 3;        // m block (32 rows)
    const int nw = wid >> 2;       // n block (64 cols)

    float acc[2][8][4];
    #pragma unroll
    for (int i = 0; i < 2; i++)
        #pragma unroll
        for (int j = 0; j < 8; j++)
            #pragma unroll
            for (int q = 0; q < 4; q++) acc[i][j][q] = 0.f;

    // stage fill: A rows (hi ch0-3 | lo ch4-7), B rows likewise.
    // 2048 cp16 per stage / 256 threads = 8 each.
    auto prefetch = [&](int stage, int kc0) {
        uint32_t sdst = sb + stage * STAGE_BYTES;
        #pragma unroll
        for (int i = 0; i < 4; i++) {
            int idx = tid + i * 256;            // 0..1023
            int row = idx >> 3;
            int ch  = idx & 7;
            cp16(sdst + sw_off(row, ch),
                 gA[ch >> 2] + (size_t)row * F_IN + kc0 + (ch & 3) * 8);
        }
        #pragma unroll
        for (int i = 0; i < 4; i++) {
            int idx = tid + i * 256;
            int row = idx >> 3;
            int ch  = idx & 7;
            cp16(sdst + A_SUB + sw_off(row, ch),
                 gB[ch >> 2] + (size_t)row * F_IN + kc0 + (ch & 3) * 8);
        }
        asm volatile("cp.async.commit_group;" ::: "memory");
    };

    prefetch(0, 0);
    prefetch(1, BK);

    const int a_row = mw * 32 + (lane & 7) + ((lane >> 3 & 1) << 3);
    const int a_chx = lane >> 4;
    const int b_row = nw * 64 + (lane & 7) + ((lane >> 4) << 3);
    const int b_chx = (lane >> 3) & 1;

    const int NCHUNK = F_IN / BK;   // 8
    int stage = 0;
    for (int c = 0; c < NCHUNK; c++) {
        if (c + 1 < NCHUNK) {
            asm volatile("cp.async.wait_group 1;" ::: "memory");
        } else {
            asm volatile("cp.async.wait_group 0;" ::: "memory");
        }
        __syncthreads();

        if (c + 2 < NCHUNK) {
            int ns = stage + 2; if (ns >= NSTAGE) ns -= NSTAGE;
            prefetch(ns, (c + 2) * BK);
        }

        const uint32_t stb = sb + stage * STAGE_BYTES;
        #pragma unroll
        for (int p = 0; p < 3; p++) {
            const int aco = (p == 2) ? 4 : 0;    // lo chunks for A
            const int bco = (p == 1) ? 4 : 0;    // lo chunks for B
            #pragma unroll
            for (int ks = 0; ks < 2; ks++) {
                const int c0 = ks * 2;
                uint32_t a[2][4];
                #pragma unroll
                for (int mi = 0; mi < 2; mi++)
                    ldm_x4(a[mi][0], a[mi][1], a[mi][2], a[mi][3],
                           stb + sw_off(a_row + mi * 16, aco + c0 + a_chx));
                uint32_t b[8][2];
                #pragma unroll
                for (int j = 0; j < 4; j++) {
                    uint32_t r0, r1, r2, r3;
                    ldm_x4(r0, r1, r2, r3,
                           stb + A_SUB + sw_off(b_row + j * 16, bco + c0 + b_chx));
                    b[2 * j][0] = r0; b[2 * j][1] = r1;
                    b[2 * j + 1][0] = r2; b[2 * j + 1][1] = r3;
                }
                #pragma unroll
                for (int mi = 0; mi < 2; mi++)
                    #pragma unroll
                    for (int ni = 0; ni < 8; ni++)
                        mma_bf16(acc[mi][ni], a[mi], b[ni]);
            }
        }
        __syncthreads();
        stage = (stage + 1 < NSTAGE) ? stage + 1 : 0;
    }

    // Epilogue: add bias; write fp16 h
    const int col0 = nw * 64 + 2 * (lane & 3);
    #pragma unroll
    for (int mi = 0; mi < 2; mi++) {
        const int rl = mw * 32 + mi * 16 + (lane >> 2);
        #pragma unroll
        for (int half = 0; half < 2; half++) {
            const int m = tile * BM + rl + half * 8;
            if (m >= MROWS) continue;
            const int bidx = m / NN;
            const int n = m - bidx * NN;
            __half* op16 = g_h16 + (size_t)n * NODE_STRIDE + bidx * (HH * FF) + head * FF;
            #pragma unroll
            for (int ni = 0; ni < 8; ni++) {
                const int col = col0 + ni * 8;
                float ox = acc[mi][ni][half * 2 + 0] + bias[head * FF + col];
                float oy = acc[mi][ni][half * 2 + 1] + bias[head * FF + col + 1];
                *(__half2*)(op16 + col) = __floats2half2_rn(ox, oy);
            }
        }
    }
}

// ---------------------------------------------------------------------------
// Aggregation (one block per src node). Fused row-range binary search.
// ---------------------------------------------------------------------------
#define ACHUNK 128
__global__ __launch_bounds__(256) void agg_kernel(
    const int* __restrict__ src,
    const int* __restrict__ dst,
    float* __restrict__ out)
{
    const int n = blockIdx.x;
    const int t = threadIdx.x;

    __shared__ int   s_e01[2];
    __shared__ int   s_dst[ACHUNK];
    __shared__ float s_w[HH][ACHUNK];
    __shared__ float s_den[HH];

    if (t == 0 || t == 32) {
        int key = n + (t >> 5);
        int lo = 0, hi = EE;
        while (lo < hi) {
            int mid = (lo + hi) >> 1;
            if (src[mid] < key) lo = mid + 1; else hi = mid;
        }
        s_e01[t >> 5] = lo;
    }
    __syncthreads();
    const int e0 = s_e01[0];
    const int e1 = s_e01[1];

    const int base = t * 8;              // 2048 elems = 256 threads * 8
    const int hi = (base >> 7) & 3;
    const int b  = base >> 9;

    float acc[8];
    #pragma unroll
    for (int j = 0; j < 8; j++) acc[j] = 0.f;
    float den_local = 0.f;

    for (int cs = e0; cs < e1; cs += ACHUNK) {
        const int m = min(cs + ACHUNK, e1) - cs;
        if (t < m) {
            int e = cs + t;
            int d = dst[e];
            s_dst[t] = d;
            #pragma unroll
            for (int h = 0; h < HH; h++) {
                float s = g_ps[h * NN + n] + g_pd[h * NN + d];
                s = (s >= 0.f) ? s : 0.2f * s;
                s = fminf(fmaxf(s, -2.f), 2.f);
                s_w[h][t] = __expf(s);
            }
        }
        __syncthreads();

        if (t < HH) {
            float sm = 0.f;
            for (int e = 0; e < m; e++) sm += s_w[t][e];
            den_local += sm;
        }

        #pragma unroll 2
        for (int e = 0; e < m; e++) {
            float w = s_w[hi][e];
            uint4 v = *(const uint4*)(g_h16 + (size_t)s_dst[e] * NODE_STRIDE + base);
            float2 f0 = __half22float2(*reinterpret_cast<__half2*>(&v.x));
            float2 f1 = __half22float2(*reinterpret_cast<__half2*>(&v.y));
            float2 f2 = __half22float2(*reinterpret_cast<__half2*>(&v.z));
            float2 f3 = __half22float2(*reinterpret_cast<__half2*>(&v.w));
            acc[0] = fmaf(w, f0.x, acc[0]);
            acc[1] = fmaf(w, f0.y, acc[1]);
            acc[2] = fmaf(w, f1.x, acc[2]);
            acc[3] = fmaf(w, f1.y, acc[3]);
            acc[4] = fmaf(w, f2.x, acc[4]);
            acc[5] = fmaf(w, f2.y, acc[5]);
            acc[6] = fmaf(w, f3.x, acc[6]);
            acc[7] = fmaf(w, f3.y, acc[7]);
        }
        __syncthreads();
    }

    if (t < HH) s_den[t] = den_local;
    __syncthreads();

    float inv = (e1 > e0) ? (1.f / s_den[hi]) : 0.f;
    float* op = out + ((size_t)b * NN + n) * CCOLS + (base & (CCOLS - 1));
    float4 o0, o1;
    o0.x = acc[0] * inv; o0.y = acc[1] * inv; o0.z = acc[2] * inv; o0.w = acc[3] * inv;
    o1.x = acc[4] * inv; o1.y = acc[5] * inv; o1.z = acc[6] * inv; o1.w = acc[7] * inv;
    ((float4*)op)[0] = o0;
    ((float4*)op)[1] = o1;
}

// ---------------------------------------------------------------------------
// Launch
// ---------------------------------------------------------------------------
extern "C" void kernel_launch(void* const* d_in, const int* in_sizes, int n_in,
                              void* d_out, int out_size)
{
    const float* x     = (const float*)d_in[0];
    const float* Wmlp  = (const float*)d_in[1];
    const float* bmlp  = (const float*)d_in[2];
    const float* Wattn = (const float*)d_in[3];
    const int*   src   = (const int*)d_in[4];
    const int*   dst   = (const int*)d_in[5];
    float*       out   = (float*)d_out;

    (void)in_sizes; (void)n_in; (void)out_size;

    cudaFuncSetAttribute(gemm_mma, cudaFuncAttributeMaxDynamicSharedMemorySize, GEMM_SMEM);

    prep_wa<<<8, 128>>>(Wmlp, bmlp, Wattn);
    prep_w<<<(HH * FF * 32 + 255) / 256, 256>>>(Wmlp);
    prep_x<<<(MPAD * 32 + 255) / 256, 256>>>(x);

    gemm_mma<<<dim3(HH, MTILES), 256, GEMM_SMEM>>>(bmlp);

    agg_kernel<<<NN, 256>>>(src, dst, out);
}

// round 11
// speedup vs baseline: 1.0817x; 1.0367x over previous
#include <cuda_runtime.h>
#include <cuda_bf16.h>
#include <cuda_fp16.h>
#include <cstdint>

// Problem constants
#define BB 4
#define NN 10000
#define EE 170000
#define F_IN 256
#define FF 128
#define HH 4
#define MROWS (BB * NN)             // 40000
#define CCOLS (HH * FF)             // 512
#define NODE_STRIDE (BB * HH * FF)  // 2048 elements per node
#define BM 128
#define MTILES 313                  // ceil(40000/128)
#define MPAD (MTILES * BM)          // 40064

// Scratch (device globals; no allocation allowed)
__device__ __align__(16) __half g_h16[(size_t)NN * NODE_STRIDE];  // fp16 h (41MB)
__device__ float g_ps[HH * NN];
__device__ float g_pd[HH * NN];
__device__ int   g_rowstart[NN + 1];
__device__ __align__(16) float g_wa[8 * F_IN];   // [src h0-3 | dst h0-3][k]
__device__ float g_wac[8];                        // bias dot a
// bf16 split images, row-major
__device__ __align__(16) __nv_bfloat16 g_Ahi[(size_t)MPAD * F_IN];
__device__ __align__(16) __nv_bfloat16 g_Alo[(size_t)MPAD * F_IN];
__device__ __align__(16) __nv_bfloat16 g_Bhi[HH * FF * F_IN];   // [head][f][k]
__device__ __align__(16) __nv_bfloat16 g_Blo[HH * FF * F_IN];

static __device__ __forceinline__ uint32_t smem_u32(const void* p) {
    uint32_t a;
    asm("{ .reg .u64 t; cvta.to.shared.u64 t, %1; cvt.u32.u64 %0, t; }" : "=r"(a) : "l"(p));
    return a;
}
static __device__ __forceinline__ void cp16(uint32_t dst, const void* src) {
    asm volatile("cp.async.cg.shared.global [%0], [%1], 16;" :: "r"(dst), "l"(src));
}
static __device__ __forceinline__ void ldm_x4(uint32_t& r0, uint32_t& r1, uint32_t& r2,
                                              uint32_t& r3, uint32_t addr) {
    asm volatile("ldmatrix.sync.aligned.m8n8.x4.shared.b16 {%0,%1,%2,%3}, [%4];"
                 : "=r"(r0), "=r"(r1), "=r"(r2), "=r"(r3) : "r"(addr));
}
static __device__ __forceinline__ void mma_bf16(float* c, const uint32_t* a, const uint32_t* b) {
    asm volatile(
        "mma.sync.aligned.m16n8k16.row.col.f32.bf16.bf16.f32 "
        "{%0,%1,%2,%3}, {%4,%5,%6,%7}, {%8,%9}, {%0,%1,%2,%3};"
        : "+f"(c[0]), "+f"(c[1]), "+f"(c[2]), "+f"(c[3])
        : "r"(a[0]), "r"(a[1]), "r"(a[2]), "r"(a[3]), "r"(b[0]), "r"(b[1]));
}

// ---------------------------------------------------------------------------
// Prep 0: Wa[vec][k] = sum_f W_mlp[h][k][f] * a_vec[h][f];  wac[vec] = b.a
// ---------------------------------------------------------------------------
__global__ __launch_bounds__(128) void prep_wa(const float* __restrict__ W,
                                               const float* __restrict__ bias,
                                               const float* __restrict__ Wattn)
{
    const int vec = blockIdx.x;          // 0..7
    const int h = vec & 3;
    const int which = vec >> 2;
    const float* a = Wattn + h * (2 * FF) + which * FF;

    for (int k = threadIdx.x; k < F_IN; k += 128) {
        const float* wr = W + (size_t)h * F_IN * FF + (size_t)k * FF;
        float s = 0.f;
        #pragma unroll 4
        for (int f = 0; f < FF; f++) s = fmaf(wr[f], a[f], s);
        g_wa[vec * F_IN + k] = s;
    }
    if (threadIdx.x == 0) {
        float c = 0.f;
        for (int f = 0; f < FF; f++) c = fmaf(bias[h * FF + f], a[f], c);
        g_wac[vec] = c;
    }
}

// ---------------------------------------------------------------------------
// Prep 1: split x into bf16 hi/lo (pad to MPAD). Fused pvec for batch B-1.
// ---------------------------------------------------------------------------
__global__ __launch_bounds__(256) void prep_x(const float* __restrict__ x)
{
    int idx = blockIdx.x * 256 + threadIdx.x;      // m*32 + kgroup
    if (idx >= MPAD * 32) return;
    int m    = idx >> 5;
    int lane = idx & 31;
    int kg   = lane << 3;

    float v[8];
    if (m < MROWS) {
        const float4* p = (const float4*)(x + (size_t)m * F_IN + kg);
        float4 a = p[0], b = p[1];
        v[0] = a.x; v[1] = a.y; v[2] = a.z; v[3] = a.w;
        v[4] = b.x; v[5] = b.y; v[6] = b.z; v[7] = b.w;
    } else {
        #pragma unroll
        for (int j = 0; j < 8; j++) v[j] = 0.f;
    }
    __nv_bfloat16 h8[8], l8[8];
    #pragma unroll
    for (int j = 0; j < 8; j++) {
        __nv_bfloat16 h = __float2bfloat16(v[j]);
        h8[j] = h;
        l8[j] = __float2bfloat16(v[j] - __bfloat162float(h));
    }
    *(uint4*)(g_Ahi + (size_t)m * F_IN + kg) = *(const uint4*)h8;
    *(uint4*)(g_Alo + (size_t)m * F_IN + kg) = *(const uint4*)l8;

    // fused pvec for batch B-1 (warp-uniform branch: warp == one m row)
    if (m >= (BB - 1) * NN && m < BB * NN) {
        float part[8];
        #pragma unroll
        for (int vec = 0; vec < 8; vec++) {
            const float* wa = g_wa + vec * F_IN + kg;
            float s = 0.f;
            #pragma unroll
            for (int j = 0; j < 8; j++) s = fmaf(v[j], wa[j], s);
            part[vec] = s;
        }
        #pragma unroll
        for (int o = 16; o > 0; o >>= 1)
            #pragma unroll
            for (int vec = 0; vec < 8; vec++)
                part[vec] += __shfl_down_sync(0xffffffffu, part[vec], o);
        if (lane == 0) {
            int n = m - (BB - 1) * NN;
            #pragma unroll
            for (int h = 0; h < 4; h++) {
                g_ps[h * NN + n] = part[h] + g_wac[h];
                g_pd[h * NN + n] = part[4 + h] + g_wac[4 + h];
            }
        }
    }
}

// ---------------------------------------------------------------------------
// Prep 2: Bt[head][f][k] = W_mlp[head][k][f], bf16 hi/lo.
// ---------------------------------------------------------------------------
__global__ __launch_bounds__(256) void prep_w(const float* __restrict__ W)
{
    int idx = blockIdx.x * 256 + threadIdx.x;      // head*4096 + f*32 + kgroup
    if (idx >= HH * FF * 32) return;
    int head = idx >> 12;
    int f    = (idx >> 5) & 127;
    int kg   = (idx & 31) << 3;

    __nv_bfloat16 h8[8], l8[8];
    #pragma unroll
    for (int j = 0; j < 8; j++) {
        float v = W[(size_t)head * F_IN * FF + (size_t)(kg + j) * FF + f];
        __nv_bfloat16 h = __float2bfloat16(v);
        h8[j] = h;
        l8[j] = __float2bfloat16(v - __bfloat162float(h));
    }
    size_t o = ((size_t)head * FF + f) * F_IN + kg;
    *(uint4*)(g_Bhi + o) = *(const uint4*)h8;
    *(uint4*)(g_Blo + o) = *(const uint4*)l8;
}

// ---------------------------------------------------------------------------
// Tensor-core GEMM (exact R6 structure): split-bf16 3-pass, CTA 128m x 128n,
// BK=64, cp.async double-buffered (128KB smem), grid (4 heads, 313 m-tiles),
// 8 warps = 4m x 2n, warp tile 32x64.
// ---------------------------------------------------------------------------
#define BK 64
#define SUB_BYTES 16384            // 128 rows * 128 B
#define STAGE_BYTES 65536
#define GEMM_SMEM 131072

static __device__ __forceinline__ uint32_t sw_off(int row, int chunk) {
    return (uint32_t)(row * 128 + ((chunk ^ (row & 7)) << 4));
}

__global__ __launch_bounds__(256, 1) void gemm_mma(const float* __restrict__ bias)
{
    extern __shared__ __align__(16) unsigned char smem[];
    const uint32_t sb = smem_u32(smem);
    const int tid  = threadIdx.x;
    const int wid  = tid >> 5;
    const int lane = tid & 31;
    const int head = blockIdx.x;
    const int tile = blockIdx.y;

    const __nv_bfloat16* gsub[4];
    gsub[0] = g_Ahi + (size_t)tile * BM * F_IN;
    gsub[1] = g_Alo + (size_t)tile * BM * F_IN;
    gsub[2] = g_Bhi + (size_t)head * FF * F_IN;
    gsub[3] = g_Blo + (size_t)head * FF * F_IN;

    const int mw = wid & 3;        // m block (32 rows)
    const int nw = wid >> 2;       // n block (64 cols)

    float acc[2][8][4];
    #pragma unroll
    for (int i = 0; i < 2; i++)
        #pragma unroll
        for (int j = 0; j < 8; j++)
            #pragma unroll
            for (int q = 0; q < 4; q++) acc[i][j][q] = 0.f;

    auto prefetch = [&](int stage, int kc0) {
        uint32_t sdst = sb + stage * STAGE_BYTES;
        #pragma unroll
        for (int sub = 0; sub < 4; sub++) {
            #pragma unroll
            for (int i = 0; i < 4; i++) {
                int idx = tid + i * 256;           // 0..1023
                int row = idx >> 3;
                int ch  = idx & 7;
                cp16(sdst + sub * SUB_BYTES + sw_off(row, ch),
                     gsub[sub] + (size_t)row * F_IN + kc0 + ch * 8);
            }
        }
        asm volatile("cp.async.commit_group;" ::: "memory");
    };

    prefetch(0, 0);

    for (int c = 0; c < 4; c++) {
        if (c + 1 < 4) {
            prefetch((c + 1) & 1, (c + 1) * BK);
            asm volatile("cp.async.wait_group 1;" ::: "memory");
        } else {
            asm volatile("cp.async.wait_group 0;" ::: "memory");
        }
        __syncthreads();

        const uint32_t stb = sb + (c & 1) * STAGE_BYTES;
        const int a_row = mw * 32 + (lane & 7) + ((lane >> 3 & 1) << 3);
        const int a_chx = lane >> 4;
        const int b_row = nw * 64 + (lane & 7) + ((lane >> 4) << 3);
        const int b_chx = (lane >> 3) & 1;

        #pragma unroll
        for (int p = 0; p < 3; p++) {
            const uint32_t abase = stb + ((p == 2) ? SUB_BYTES : 0);
            const uint32_t bbase = stb + 2 * SUB_BYTES + ((p == 1) ? SUB_BYTES : 0);
            #pragma unroll
            for (int ks = 0; ks < 4; ks++) {
                const int c0 = ks * 2;
                uint32_t a[2][4];
                #pragma unroll
                for (int mi = 0; mi < 2; mi++)
                    ldm_x4(a[mi][0], a[mi][1], a[mi][2], a[mi][3],
                           abase + sw_off(a_row + mi * 16, c0 + a_chx));
                uint32_t b[8][2];
                #pragma unroll
                for (int j = 0; j < 4; j++) {
                    uint32_t r0, r1, r2, r3;
                    ldm_x4(r0, r1, r2, r3,
                           bbase + sw_off(b_row + j * 16, c0 + b_chx));
                    b[2 * j][0] = r0; b[2 * j][1] = r1;
                    b[2 * j + 1][0] = r2; b[2 * j + 1][1] = r3;
                }
                #pragma unroll
                for (int mi = 0; mi < 2; mi++)
                    #pragma unroll
                    for (int ni = 0; ni < 8; ni++)
                        mma_bf16(acc[mi][ni], a[mi], b[ni]);
            }
        }
        __syncthreads();
    }

    // Epilogue: add bias; write fp16 h only
    const int col0 = nw * 64 + 2 * (lane & 3);
    #pragma unroll
    for (int mi = 0; mi < 2; mi++) {
        const int rl = mw * 32 + mi * 16 + (lane >> 2);
        #pragma unroll
        for (int half = 0; half < 2; half++) {
            const int m = tile * BM + rl + half * 8;
            if (m >= MROWS) continue;
            const int bidx = m / NN;
            const int n = m - bidx * NN;
            __half* op16 = g_h16 + (size_t)n * NODE_STRIDE + bidx * (HH * FF) + head * FF;
            #pragma unroll
            for (int ni = 0; ni < 8; ni++) {
                const int col = col0 + ni * 8;
                float ox = acc[mi][ni][half * 2 + 0] + bias[head * FF + col];
                float oy = acc[mi][ni][half * 2 + 1] + bias[head * FF + col + 1];
                *(__half2*)(op16 + col) = __floats2half2_rn(ox, oy);
            }
        }
    }
}

// ---------------------------------------------------------------------------
// row_start via binary search (src sorted) — separate, massively parallel
// ---------------------------------------------------------------------------
__global__ void rowstart_kernel(const int* __restrict__ src)
{
    int n = blockIdx.x * blockDim.x + threadIdx.x;
    if (n > NN) return;
    int lo = 0, hi = EE;
    while (lo < hi) {
        int mid = (lo + hi) >> 1;
        if (src[mid] < n) lo = mid + 1; else hi = mid;
    }
    g_rowstart[n] = lo;
}

// ---------------------------------------------------------------------------
// Aggregation (one block per src node), fp16 gather, fp32 accum.
// ---------------------------------------------------------------------------
#define ACHUNK 128
__global__ __launch_bounds__(256) void agg_kernel(
    const int* __restrict__ dst,
    float* __restrict__ out)
{
    const int n = blockIdx.x;
    const int t = threadIdx.x;
    const int e0 = g_rowstart[n];
    const int e1 = g_rowstart[n + 1];

    const int base = t * 8;              // 2048 elems = 256 threads * 8
    const int hi = (base >> 7) & 3;
    const int b  = base >> 9;

    __shared__ int   s_dst[ACHUNK];
    __shared__ float s_w[HH][ACHUNK];
    __shared__ float s_den[HH];

    float acc[8];
    #pragma unroll
    for (int j = 0; j < 8; j++) acc[j] = 0.f;
    float den_local = 0.f;

    for (int cs = e0; cs < e1; cs += ACHUNK) {
        const int m = min(cs + ACHUNK, e1) - cs;
        if (t < m) {
            int e = cs + t;
            int d = dst[e];
            s_dst[t] = d;
            #pragma unroll
            for (int h = 0; h < HH; h++) {
                float s = g_ps[h * NN + n] + g_pd[h * NN + d];
                s = (s >= 0.f) ? s : 0.2f * s;
                s = fminf(fmaxf(s, -2.f), 2.f);
                s_w[h][t] = __expf(s);
            }
        }
        __syncthreads();

        if (t < HH) {
            float sm = 0.f;
            for (int e = 0; e < m; e++) sm += s_w[t][e];
            den_local += sm;
        }

        #pragma unroll 2
        for (int e = 0; e < m; e++) {
            float w = s_w[hi][e];
            uint4 v = *(const uint4*)(g_h16 + (size_t)s_dst[e] * NODE_STRIDE + base);
            float2 f0 = __half22float2(*reinterpret_cast<__half2*>(&v.x));
            float2 f1 = __half22float2(*reinterpret_cast<__half2*>(&v.y));
            float2 f2 = __half22float2(*reinterpret_cast<__half2*>(&v.z));
            float2 f3 = __half22float2(*reinterpret_cast<__half2*>(&v.w));
            acc[0] = fmaf(w, f0.x, acc[0]);
            acc[1] = fmaf(w, f0.y, acc[1]);
            acc[2] = fmaf(w, f1.x, acc[2]);
            acc[3] = fmaf(w, f1.y, acc[3]);
            acc[4] = fmaf(w, f2.x, acc[4]);
            acc[5] = fmaf(w, f2.y, acc[5]);
            acc[6] = fmaf(w, f3.x, acc[6]);
            acc[7] = fmaf(w, f3.y, acc[7]);
        }
        __syncthreads();
    }

    if (t < HH) s_den[t] = den_local;
    __syncthreads();

    float inv = (e1 > e0) ? (1.f / s_den[hi]) : 0.f;
    float* op = out + ((size_t)b * NN + n) * CCOLS + (base & (CCOLS - 1));
    float4 o0, o1;
    o0.x = acc[0] * inv; o0.y = acc[1] * inv; o0.z = acc[2] * inv; o0.w = acc[3] * inv;
    o1.x = acc[4] * inv; o1.y = acc[5] * inv; o1.z = acc[6] * inv; o1.w = acc[7] * inv;
    ((float4*)op)[0] = o0;
    ((float4*)op)[1] = o1;
}

// ---------------------------------------------------------------------------
// Launch
// ---------------------------------------------------------------------------
extern "C" void kernel_launch(void* const* d_in, const int* in_sizes, int n_in,
                              void* d_out, int out_size)
{
    const float* x     = (const float*)d_in[0];
    const float* Wmlp  = (const float*)d_in[1];
    const float* bmlp  = (const float*)d_in[2];
    const float* Wattn = (const float*)d_in[3];
    const int*   src   = (const int*)d_in[4];
    const int*   dst   = (const int*)d_in[5];
    float*       out   = (float*)d_out;

    (void)in_sizes; (void)n_in; (void)out_size;

    cudaFuncSetAttribute(gemm_mma, cudaFuncAttributeMaxDynamicSharedMemorySize, GEMM_SMEM);

    prep_wa<<<8, 128>>>(Wmlp, bmlp, Wattn);
    prep_w<<<(HH * FF * 32 + 255) / 256, 256>>>(Wmlp);
    prep_x<<<(MPAD * 32 + 255) / 256, 256>>>(x);
    rowstart_kernel<<<(NN + 1 + 255) / 256, 256>>>(src);

    gemm_mma<<<dim3(HH, MTILES), 256, GEMM_SMEM>>>(bmlp);

    agg_kernel<<<NN, 256>>>(dst, out);
}

// round 13
// speedup vs baseline: 1.2236x; 1.1312x over previous
#include <cuda_runtime.h>
#include <cuda_bf16.h>
#include <cuda_fp16.h>
#include <cstdint>

// Problem constants
#define BB 4
#define NN 10000
#define EE 170000
#define F_IN 256
#define FF 128
#define HH 4
#define MROWS (BB * NN)             // 40000
#define CCOLS (HH * FF)             // 512
#define NODE_STRIDE (BB * HH * FF)  // 2048 elements per node
#define BM 128
#define BN 64
#define MTILES 313                  // ceil(40000/128)
#define MPAD (MTILES * BM)          // 40064

// Merged-prep block ranges
#define PXB 5008                    // prep_x blocks: MPAD*32/256
#define PWB 64                      // prep_w blocks
#define PAB 8                       // prep_wa blocks
#define RSB 40                      // rowstart blocks
#define PREP_BLOCKS (PXB + PWB + PAB + RSB)

// Scratch (device globals; no allocation allowed)
__device__ __align__(16) __half g_h16[(size_t)NN * NODE_STRIDE];  // fp16 h (41MB)
__device__ float g_ps[HH * NN];
__device__ float g_pd[HH * NN];
__device__ int   g_rowstart[NN + 1];
__device__ __align__(16) float g_wa[8 * F_IN];   // [src h0-3 | dst h0-3][k]
__device__ float g_wac[8];                        // bias dot a
// bf16 split images, row-major
__device__ __align__(16) __nv_bfloat16 g_Ahi[(size_t)MPAD * F_IN];
__device__ __align__(16) __nv_bfloat16 g_Alo[(size_t)MPAD * F_IN];
__device__ __align__(16) __nv_bfloat16 g_Bhi[HH * FF * F_IN];   // [head][f][k]
__device__ __align__(16) __nv_bfloat16 g_Blo[HH * FF * F_IN];

static __device__ __forceinline__ uint32_t smem_u32(const void* p) {
    uint32_t a;
    asm("{ .reg .u64 t; cvta.to.shared.u64 t, %1; cvt.u32.u64 %0, t; }" : "=r"(a) : "l"(p));
    return a;
}
static __device__ __forceinline__ void cp16(uint32_t dst, const void* src) {
    asm volatile("cp.async.cg.shared.global [%0], [%1], 16;" :: "r"(dst), "l"(src));
}
static __device__ __forceinline__ void ldm_x4(uint32_t& r0, uint32_t& r1, uint32_t& r2,
                                              uint32_t& r3, uint32_t addr) {
    asm volatile("ldmatrix.sync.aligned.m8n8.x4.shared.b16 {%0,%1,%2,%3}, [%4];"
                 : "=r"(r0), "=r"(r1), "=r"(r2), "=r"(r3) : "r"(addr));
}
static __device__ __forceinline__ void mma_bf16(float* c, const uint32_t* a, const uint32_t* b) {
    asm volatile(
        "mma.sync.aligned.m16n8k16.row.col.f32.bf16.bf16.f32 "
        "{%0,%1,%2,%3}, {%4,%5,%6,%7}, {%8,%9}, {%0,%1,%2,%3};"
        : "+f"(c[0]), "+f"(c[1]), "+f"(c[2]), "+f"(c[3])
        : "r"(a[0]), "r"(a[1]), "r"(a[2]), "r"(a[3]), "r"(b[0]), "r"(b[1]));
}

// ---------------------------------------------------------------------------
// Merged prep: one launch, block-range dispatch.
//  [0, PXB)            : split x -> bf16 hi/lo images (pad to MPAD)
//  [PXB, +PWB)         : Bt[head][f][k] = W[head][k][f], bf16 hi/lo
//  [PXB+PWB, +PAB)     : Wa[vec][k] = sum_f W[h][k][f]*a[h][f]; wac = b.a
//  [PXB+PWB+PAB, +RSB) : rowstart binary search (src sorted)
// All parts independent (read only kernel inputs).
// ---------------------------------------------------------------------------
__global__ __launch_bounds__(256) void prep_all(const float* __restrict__ x,
                                                const float* __restrict__ W,
                                                const float* __restrict__ bias,
                                                const float* __restrict__ Wattn,
                                                const int* __restrict__ src)
{
    const int blk = blockIdx.x;
    const int tid = threadIdx.x;

    if (blk < PXB) {
        // ---- prep_x ----
        int idx = blk * 256 + tid;           // m*32 + kgroup
        int m  = idx >> 5;
        int kg = (idx & 31) << 3;

        float v[8];
        if (m < MROWS) {
            const float4* p = (const float4*)(x + (size_t)m * F_IN + kg);
            float4 a = p[0], b = p[1];
            v[0] = a.x; v[1] = a.y; v[2] = a.z; v[3] = a.w;
            v[4] = b.x; v[5] = b.y; v[6] = b.z; v[7] = b.w;
        } else {
            #pragma unroll
            for (int j = 0; j < 8; j++) v[j] = 0.f;
        }
        __nv_bfloat16 h8[8], l8[8];
        #pragma unroll
        for (int j = 0; j < 8; j++) {
            __nv_bfloat16 h = __float2bfloat16(v[j]);
            h8[j] = h;
            l8[j] = __float2bfloat16(v[j] - __bfloat162float(h));
        }
        *(uint4*)(g_Ahi + (size_t)m * F_IN + kg) = *(const uint4*)h8;
        *(uint4*)(g_Alo + (size_t)m * F_IN + kg) = *(const uint4*)l8;
    } else if (blk < PXB + PWB) {
        // ---- prep_w ----
        int idx = (blk - PXB) * 256 + tid;   // head*4096 + f*32 + kgroup
        int head = idx >> 12;
        int f    = (idx >> 5) & 127;
        int kg   = (idx & 31) << 3;

        __nv_bfloat16 h8[8], l8[8];
        #pragma unroll
        for (int j = 0; j < 8; j++) {
            float v = W[(size_t)head * F_IN * FF + (size_t)(kg + j) * FF + f];
            __nv_bfloat16 h = __float2bfloat16(v);
            h8[j] = h;
            l8[j] = __float2bfloat16(v - __bfloat162float(h));
        }
        size_t o = ((size_t)head * FF + f) * F_IN + kg;
        *(uint4*)(g_Bhi + o) = *(const uint4*)h8;
        *(uint4*)(g_Blo + o) = *(const uint4*)l8;
    } else if (blk < PXB + PWB + PAB) {
        // ---- prep_wa ----
        const int vec = blk - PXB - PWB;     // 0..7
        const int h = vec & 3;
        const int which = vec >> 2;
        const float* a = Wattn + h * (2 * FF) + which * FF;

        int k = tid;                         // 256 threads, 256 k values
        const float* wr = W + (size_t)h * F_IN * FF + (size_t)k * FF;
        float s = 0.f;
        #pragma unroll 4
        for (int f = 0; f < FF; f++) s = fmaf(wr[f], a[f], s);
        g_wa[vec * F_IN + k] = s;
        if (tid == 0) {
            float c = 0.f;
            for (int f = 0; f < FF; f++) c = fmaf(bias[h * FF + f], a[f], c);
            g_wac[vec] = c;
        }
    } else {
        // ---- rowstart ----
        int n = (blk - PXB - PWB - PAB) * 256 + tid;
        if (n > NN) return;
        int lo = 0, hi = EE;
        while (lo < hi) {
            int mid = (lo + hi) >> 1;
            if (src[mid] < n) lo = mid + 1; else hi = mid;
        }
        g_rowstart[n] = lo;
    }
}

// ---------------------------------------------------------------------------
// pvec: p_src/p_dst[h][n] = x[B-1][n][:] . Wa[vec][:] + wac[vec]
// One warp per node; 8 warps per block.
// ---------------------------------------------------------------------------
__global__ __launch_bounds__(256) void pvec_kernel(const float* __restrict__ x)
{
    const int warp = (blockIdx.x * 256 + threadIdx.x) >> 5;
    const int lane = threadIdx.x & 31;
    if (warp >= NN) return;
    const int n = warp;
    const int kg = lane << 3;

    float v[8];
    const float4* p = (const float4*)(x + ((size_t)(BB - 1) * NN + n) * F_IN + kg);
    float4 a = p[0], b = p[1];
    v[0] = a.x; v[1] = a.y; v[2] = a.z; v[3] = a.w;
    v[4] = b.x; v[5] = b.y; v[6] = b.z; v[7] = b.w;

    float part[8];
    #pragma unroll
    for (int vec = 0; vec < 8; vec++) {
        const float* wa = g_wa + vec * F_IN + kg;
        float s = 0.f;
        #pragma unroll
        for (int j = 0; j < 8; j++) s = fmaf(v[j], wa[j], s);
        part[vec] = s;
    }
    #pragma unroll
    for (int o = 16; o > 0; o >>= 1)
        #pragma unroll
        for (int vec = 0; vec < 8; vec++)
            part[vec] += __shfl_down_sync(0xffffffffu, part[vec], o);
    if (lane == 0) {
        #pragma unroll
        for (int h = 0; h < 4; h++) {
            g_ps[h * NN + n] = part[h] + g_wac[h];
            g_pd[h * NN + n] = part[4 + h] + g_wac[4 + h];
        }
    }
}

// ---------------------------------------------------------------------------
// Tensor-core GEMM, split-bf16 3-pass. CTA 128m x 64n, BK=64, 2-stage
// cp.async double-buffer. Stage = A(hi+lo) 32KB + B(hi+lo) 16KB = 48KB;
// 96KB total -> 2 CTAs/SM. 8 warps = 4m x 2n; warp tile 32x32.
// grid = (HH*2 [head x n-half], MTILES).
// ---------------------------------------------------------------------------
#define BK 64
#define A_SUB 16384                // 128 rows * 128 B
#define B_SUB 8192                 // 64 rows * 128 B
#define STAGE_BYTES (2 * A_SUB + 2 * B_SUB)   // 49152
#define GEMM_SMEM (2 * STAGE_BYTES)           // 98304

static __device__ __forceinline__ uint32_t sw_off(int row, int chunk) {
    return (uint32_t)(row * 128 + ((chunk ^ (row & 7)) << 4));
}

__global__ __launch_bounds__(256, 2) void gemm_mma(const float* __restrict__ bias)
{
    extern __shared__ __align__(16) unsigned char smem[];
    const uint32_t sb = smem_u32(smem);
    const int tid  = threadIdx.x;
    const int wid  = tid >> 5;
    const int lane = tid & 31;
    const int head = blockIdx.x >> 1;
    const int nh   = blockIdx.x & 1;      // which 64-col half of the head
    const int tile = blockIdx.y;

    const __nv_bfloat16* gA[2];
    const __nv_bfloat16* gB[2];
    gA[0] = g_Ahi + (size_t)tile * BM * F_IN;
    gA[1] = g_Alo + (size_t)tile * BM * F_IN;
    gB[0] = g_Bhi + ((size_t)head * FF + nh * BN) * F_IN;
    gB[1] = g_Blo + ((size_t)head * FF + nh * BN) * F_IN;

    const int mw = wid & 3;        // m block (32 rows)
    const int nw = wid >> 2;       // n block (32 cols)

    float acc[2][4][4];
    #pragma unroll
    for (int i = 0; i < 2; i++)
        #pragma unroll
        for (int j = 0; j < 4; j++)
            #pragma unroll
            for (int q = 0; q < 4; q++) acc[i][j][q] = 0.f;

    // stage fill: A 2048 cp16 + B 1024 cp16 = 3072 / 256 threads = 12 each
    auto prefetch = [&](int stage, int kc0) {
        uint32_t sdst = sb + stage * STAGE_BYTES;
        #pragma unroll
        for (int sub = 0; sub < 2; sub++) {
            #pragma unroll
            for (int i = 0; i < 4; i++) {
                int idx = tid + i * 256;           // 0..1023
                int row = idx >> 3;
                int ch  = idx & 7;
                cp16(sdst + sub * A_SUB + sw_off(row, ch),
                     gA[sub] + (size_t)row * F_IN + kc0 + ch * 8);
            }
        }
        #pragma unroll
        for (int sub = 0; sub < 2; sub++) {
            #pragma unroll
            for (int i = 0; i < 2; i++) {
                int idx = tid + i * 256;           // 0..511
                int row = idx >> 3;                // 0..63
                int ch  = idx & 7;
                cp16(sdst + 2 * A_SUB + sub * B_SUB + sw_off(row, ch),
                     gB[sub] + (size_t)row * F_IN + kc0 + ch * 8);
            }
        }
        asm volatile("cp.async.commit_group;" ::: "memory");
    };

    prefetch(0, 0);

    for (int c = 0; c < 4; c++) {
        if (c + 1 < 4) {
            prefetch((c + 1) & 1, (c + 1) * BK);
            asm volatile("cp.async.wait_group 1;" ::: "memory");
        } else {
            asm volatile("cp.async.wait_group 0;" ::: "memory");
        }
        __syncthreads();

        const uint32_t stb = sb + (c & 1) * STAGE_BYTES;
        const int a_row = mw * 32 + (lane & 7) + ((lane >> 3 & 1) << 3);
        const int a_chx = lane >> 4;
        const int b_row = nw * 32 + (lane & 7) + ((lane >> 4) << 3);
        const int b_chx = (lane >> 3) & 1;

        #pragma unroll
        for (int p = 0; p < 3; p++) {
            const uint32_t abase = stb + ((p == 2) ? A_SUB : 0);
            const uint32_t bbase = stb + 2 * A_SUB + ((p == 1) ? B_SUB : 0);
            #pragma unroll
            for (int ks = 0; ks < 4; ks++) {
                const int c0 = ks * 2;
                uint32_t a[2][4];
                #pragma unroll
                for (int mi = 0; mi < 2; mi++)
                    ldm_x4(a[mi][0], a[mi][1], a[mi][2], a[mi][3],
                           abase + sw_off(a_row + mi * 16, c0 + a_chx));
                uint32_t b[4][2];
                #pragma unroll
                for (int j = 0; j < 2; j++) {
                    uint32_t r0, r1, r2, r3;
                    ldm_x4(r0, r1, r2, r3,
                           bbase + sw_off(b_row + j * 16, c0 + b_chx));
                    b[2 * j][0] = r0; b[2 * j][1] = r1;
                    b[2 * j + 1][0] = r2; b[2 * j + 1][1] = r3;
                }
                #pragma unroll
                for (int mi = 0; mi < 2; mi++)
                    #pragma unroll
                    for (int ni = 0; ni < 4; ni++)
                        mma_bf16(acc[mi][ni], a[mi], b[ni]);
            }
        }
        __syncthreads();
    }

    // Epilogue: add bias; write fp16 h
    const int col0 = nw * 32 + 2 * (lane & 3);   // within 64-col half
    #pragma unroll
    for (int mi = 0; mi < 2; mi++) {
        const int rl = mw * 32 + mi * 16 + (lane >> 2);
        #pragma unroll
        for (int half = 0; half < 2; half++) {
            const int m = tile * BM + rl + half * 8;
            if (m >= MROWS) continue;
            const int bidx = m / NN;
            const int n = m - bidx * NN;
            __half* op16 = g_h16 + (size_t)n * NODE_STRIDE + bidx * (HH * FF)
                         + head * FF + nh * BN;
            const float* bp = bias + head * FF + nh * BN;
            #pragma unroll
            for (int ni = 0; ni < 4; ni++) {
                const int col = col0 + ni * 8;
                float ox = acc[mi][ni][half * 2 + 0] + bp[col];
                float oy = acc[mi][ni][half * 2 + 1] + bp[col + 1];
                *(__half2*)(op16 + col) = __floats2half2_rn(ox, oy);
            }
        }
    }
}

// ---------------------------------------------------------------------------
// Aggregation (one block per src node), fp16 gather, fp32 accum.
// ---------------------------------------------------------------------------
#define ACHUNK 128
__global__ __launch_bounds__(256) void agg_kernel(
    const int* __restrict__ dst,
    float* __restrict__ out)
{
    const int n = blockIdx.x;
    const int t = threadIdx.x;
    const int e0 = g_rowstart[n];
    const int e1 = g_rowstart[n + 1];

    const int base = t * 8;              // 2048 elems = 256 threads * 8
    const int hi = (base >> 7) & 3;
    const int b  = base >> 9;

    __shared__ int   s_dst[ACHUNK];
    __shared__ float s_w[HH][ACHUNK];
    __shared__ float s_den[HH];

    float acc[8];
    #pragma unroll
    for (int j = 0; j < 8; j++) acc[j] = 0.f;
    float den_local = 0.f;

    for (int cs = e0; cs < e1; cs += ACHUNK) {
        const int m = min(cs + ACHUNK, e1) - cs;
        if (t < m) {
            int e = cs + t;
            int d = dst[e];
            s_dst[t] = d;
            #pragma unroll
            for (int h = 0; h < HH; h++) {
                float s = g_ps[h * NN + n] + g_pd[h * NN + d];
                s = (s >= 0.f) ? s : 0.2f * s;
                s = fminf(fmaxf(s, -2.f), 2.f);
                s_w[h][t] = __expf(s);
            }
        }
        __syncthreads();

        if (t < HH) {
            float sm = 0.f;
            for (int e = 0; e < m; e++) sm += s_w[t][e];
            den_local += sm;
        }

        #pragma unroll 2
        for (int e = 0; e < m; e++) {
            float w = s_w[hi][e];
            uint4 v = *(const uint4*)(g_h16 + (size_t)s_dst[e] * NODE_STRIDE + base);
            float2 f0 = __half22float2(*reinterpret_cast<__half2*>(&v.x));
            float2 f1 = __half22float2(*reinterpret_cast<__half2*>(&v.y));
            float2 f2 = __half22float2(*reinterpret_cast<__half2*>(&v.z));
            float2 f3 = __half22float2(*reinterpret_cast<__half2*>(&v.w));
            acc[0] = fmaf(w, f0.x, acc[0]);
            acc[1] = fmaf(w, f0.y, acc[1]);
            acc[2] = fmaf(w, f1.x, acc[2]);
            acc[3] = fmaf(w, f1.y, acc[3]);
            acc[4] = fmaf(w, f2.x, acc[4]);
            acc[5] = fmaf(w, f2.y, acc[5]);
            acc[6] = fmaf(w, f3.x, acc[6]);
            acc[7] = fmaf(w, f3.y, acc[7]);
        }
        __syncthreads();
    }

    if (t < HH) s_den[t] = den_local;
    __syncthreads();

    float inv = (e1 > e0) ? (1.f / s_den[hi]) : 0.f;
    float* op = out + ((size_t)b * NN + n) * CCOLS + (base & (CCOLS - 1));
    float4 o0, o1;
    o0.x = acc[0] * inv; o0.y = acc[1] * inv; o0.z = acc[2] * inv; o0.w = acc[3] * inv;
    o1.x = acc[4] * inv; o1.y = acc[5] * inv; o1.z = acc[6] * inv; o1.w = acc[7] * inv;
    ((float4*)op)[0] = o0;
    ((float4*)op)[1] = o1;
}

// ---------------------------------------------------------------------------
// Launch
// ---------------------------------------------------------------------------
extern "C" void kernel_launch(void* const* d_in, const int* in_sizes, int n_in,
                              void* d_out, int out_size)
{
    const float* x     = (const float*)d_in[0];
    const float* Wmlp  = (const float*)d_in[1];
    const float* bmlp  = (const float*)d_in[2];
    const float* Wattn = (const float*)d_in[3];
    const int*   src   = (const int*)d_in[4];
    const int*   dst   = (const int*)d_in[5];
    float*       out   = (float*)d_out;

    (void)in_sizes; (void)n_in; (void)out_size;

    cudaFuncSetAttribute(gemm_mma, cudaFuncAttributeMaxDynamicSharedMemorySize, GEMM_SMEM);

    prep_all<<<PREP_BLOCKS, 256>>>(x, Wmlp, bmlp, Wattn, src);
    pvec_kernel<<<(NN + 7) / 8, 256>>>(x);

    gemm_mma<<<dim3(HH * 2, MTILES), 256, GEMM_SMEM>>>(bmlp);

    agg_kernel<<<NN, 256>>>(dst, out);
}

// round 14
// speedup vs baseline: 1.6730x; 1.3673x over previous
#include <cuda_runtime.h>
#include <cuda_bf16.h>
#include <cuda_fp16.h>
#include <cstdint>

// Problem constants
#define BB 4
#define NN 10000
#define EE 170000
#define F_IN 256
#define FF 128
#define HH 4
#define MROWS (BB * NN)             // 40000
#define CCOLS (HH * FF)             // 512
#define NODE_STRIDE (BB * HH * FF)  // 2048 elements per node
#define BM 128
#define BN 64
#define MTILES 313                  // ceil(40000/128)
#define MPAD (MTILES * BM)          // 40064

// Merged-prep block ranges
#define PXB 5008                    // prep_x blocks: MPAD*32/256
#define PWB 64                      // prep_w blocks
#define PAB 8                       // prep_wa blocks
#define RSB 40                      // rowstart blocks
#define PREP_BLOCKS (PXB + PWB + PAB + RSB)

// Scratch (device globals; no allocation allowed)
__device__ __align__(16) __half g_h16[(size_t)NN * NODE_STRIDE];  // fp16 h (41MB)
__device__ float g_ps[HH * NN];
__device__ float g_pd[HH * NN];
__device__ int   g_rowstart[NN + 1];
__device__ __align__(16) float g_wa[8 * F_IN];   // [src h0-3 | dst h0-3][k]
__device__ float g_wac[8];                        // bias dot a
// fp16 images, row-major (single precision level — fp16 mma pass)
__device__ __align__(16) __half g_Ah[(size_t)MPAD * F_IN];
__device__ __align__(16) __half g_Bh[HH * FF * F_IN];   // [head][f][k]

static __device__ __forceinline__ uint32_t smem_u32(const void* p) {
    uint32_t a;
    asm("{ .reg .u64 t; cvta.to.shared.u64 t, %1; cvt.u32.u64 %0, t; }" : "=r"(a) : "l"(p));
    return a;
}
static __device__ __forceinline__ void cp16(uint32_t dst, const void* src) {
    asm volatile("cp.async.cg.shared.global [%0], [%1], 16;" :: "r"(dst), "l"(src));
}
static __device__ __forceinline__ void ldm_x4(uint32_t& r0, uint32_t& r1, uint32_t& r2,
                                              uint32_t& r3, uint32_t addr) {
    asm volatile("ldmatrix.sync.aligned.m8n8.x4.shared.b16 {%0,%1,%2,%3}, [%4];"
                 : "=r"(r0), "=r"(r1), "=r"(r2), "=r"(r3) : "r"(addr));
}
static __device__ __forceinline__ void mma_f16(float* c, const uint32_t* a, const uint32_t* b) {
    asm volatile(
        "mma.sync.aligned.m16n8k16.row.col.f32.f16.f16.f32 "
        "{%0,%1,%2,%3}, {%4,%5,%6,%7}, {%8,%9}, {%0,%1,%2,%3};"
        : "+f"(c[0]), "+f"(c[1]), "+f"(c[2]), "+f"(c[3])
        : "r"(a[0]), "r"(a[1]), "r"(a[2]), "r"(a[3]), "r"(b[0]), "r"(b[1]));
}

// ---------------------------------------------------------------------------
// Merged prep: one launch, block-range dispatch.
//  [0, PXB)            : x -> fp16 image (pad to MPAD)
//  [PXB, +PWB)         : Bt[head][f][k] = W[head][k][f], fp16
//  [PXB+PWB, +PAB)     : Wa[vec][k] = sum_f W[h][k][f]*a[h][f]; wac = b.a
//  [PXB+PWB+PAB, +RSB) : rowstart binary search (src sorted)
// ---------------------------------------------------------------------------
__global__ __launch_bounds__(256) void prep_all(const float* __restrict__ x,
                                                const float* __restrict__ W,
                                                const float* __restrict__ bias,
                                                const float* __restrict__ Wattn,
                                                const int* __restrict__ src)
{
    const int blk = blockIdx.x;
    const int tid = threadIdx.x;

    if (blk < PXB) {
        // ---- prep_x ----
        int idx = blk * 256 + tid;           // m*32 + kgroup
        int m  = idx >> 5;
        int kg = (idx & 31) << 3;

        float v[8];
        if (m < MROWS) {
            const float4* p = (const float4*)(x + (size_t)m * F_IN + kg);
            float4 a = p[0], b = p[1];
            v[0] = a.x; v[1] = a.y; v[2] = a.z; v[3] = a.w;
            v[4] = b.x; v[5] = b.y; v[6] = b.z; v[7] = b.w;
        } else {
            #pragma unroll
            for (int j = 0; j < 8; j++) v[j] = 0.f;
        }
        __half h8[8];
        #pragma unroll
        for (int j = 0; j < 8; j++) h8[j] = __float2half_rn(v[j]);
        *(uint4*)(g_Ah + (size_t)m * F_IN + kg) = *(const uint4*)h8;
    } else if (blk < PXB + PWB) {
        // ---- prep_w ----
        int idx = (blk - PXB) * 256 + tid;   // head*4096 + f*32 + kgroup
        int head = idx >> 12;
        int f    = (idx >> 5) & 127;
        int kg   = (idx & 31) << 3;

        __half h8[8];
        #pragma unroll
        for (int j = 0; j < 8; j++)
            h8[j] = __float2half_rn(W[(size_t)head * F_IN * FF + (size_t)(kg + j) * FF + f]);
        *(uint4*)(g_Bh + ((size_t)head * FF + f) * F_IN + kg) = *(const uint4*)h8;
    } else if (blk < PXB + PWB + PAB) {
        // ---- prep_wa ----
        const int vec = blk - PXB - PWB;     // 0..7
        const int h = vec & 3;
        const int which = vec >> 2;
        const float* a = Wattn + h * (2 * FF) + which * FF;

        int k = tid;                         // 256 threads, 256 k values
        const float* wr = W + (size_t)h * F_IN * FF + (size_t)k * FF;
        float s = 0.f;
        #pragma unroll 4
        for (int f = 0; f < FF; f++) s = fmaf(wr[f], a[f], s);
        g_wa[vec * F_IN + k] = s;
        if (tid == 0) {
            float c = 0.f;
            for (int f = 0; f < FF; f++) c = fmaf(bias[h * FF + f], a[f], c);
            g_wac[vec] = c;
        }
    } else {
        // ---- rowstart ----
        int n = (blk - PXB - PWB - PAB) * 256 + tid;
        if (n > NN) return;
        int lo = 0, hi = EE;
        while (lo < hi) {
            int mid = (lo + hi) >> 1;
            if (src[mid] < n) lo = mid + 1; else hi = mid;
        }
        g_rowstart[n] = lo;
    }
}

// ---------------------------------------------------------------------------
// pvec: p_src/p_dst[h][n] = x[B-1][n][:] . Wa[vec][:] + wac[vec]  (fp32 exact)
// ---------------------------------------------------------------------------
__global__ __launch_bounds__(256) void pvec_kernel(const float* __restrict__ x)
{
    const int warp = (blockIdx.x * 256 + threadIdx.x) >> 5;
    const int lane = threadIdx.x & 31;
    if (warp >= NN) return;
    const int n = warp;
    const int kg = lane << 3;

    float v[8];
    const float4* p = (const float4*)(x + ((size_t)(BB - 1) * NN + n) * F_IN + kg);
    float4 a = p[0], b = p[1];
    v[0] = a.x; v[1] = a.y; v[2] = a.z; v[3] = a.w;
    v[4] = b.x; v[5] = b.y; v[6] = b.z; v[7] = b.w;

    float part[8];
    #pragma unroll
    for (int vec = 0; vec < 8; vec++) {
        const float* wa = g_wa + vec * F_IN + kg;
        float s = 0.f;
        #pragma unroll
        for (int j = 0; j < 8; j++) s = fmaf(v[j], wa[j], s);
        part[vec] = s;
    }
    #pragma unroll
    for (int o = 16; o > 0; o >>= 1)
        #pragma unroll
        for (int vec = 0; vec < 8; vec++)
            part[vec] += __shfl_down_sync(0xffffffffu, part[vec], o);
    if (lane == 0) {
        #pragma unroll
        for (int h = 0; h < 4; h++) {
            g_ps[h * NN + n] = part[h] + g_wac[h];
            g_pd[h * NN + n] = part[4 + h] + g_wac[4 + h];
        }
    }
}

// ---------------------------------------------------------------------------
// Tensor-core GEMM, single-pass fp16 (fp32 accum). CTA 128m x 64n, BK=64,
// 4 stages (whole K prefetched upfront, 96KB smem -> 2 CTAs/SM).
// 8 warps = 4m x 2n; warp tile 32x32. grid = (HH*2, MTILES).
// ---------------------------------------------------------------------------
#define BK 64
#define A_SUB 16384                // 128 rows * 128 B
#define B_SUB 8192                 // 64 rows * 128 B
#define STAGE_BYTES (A_SUB + B_SUB)           // 24576
#define NSTAGE 4
#define GEMM_SMEM (NSTAGE * STAGE_BYTES)      // 98304

static __device__ __forceinline__ uint32_t sw_off(int row, int chunk) {
    return (uint32_t)(row * 128 + ((chunk ^ (row & 7)) << 4));
}

__global__ __launch_bounds__(256, 2) void gemm_mma(const float* __restrict__ bias)
{
    extern __shared__ __align__(16) unsigned char smem[];
    const uint32_t sb = smem_u32(smem);
    const int tid  = threadIdx.x;
    const int wid  = tid >> 5;
    const int lane = tid & 31;
    const int head = blockIdx.x >> 1;
    const int nh   = blockIdx.x & 1;      // which 64-col half of the head
    const int tile = blockIdx.y;

    const __half* gA = g_Ah + (size_t)tile * BM * F_IN;
    const __half* gB = g_Bh + ((size_t)head * FF + nh * BN) * F_IN;

    const int mw = wid & 3;        // m block (32 rows)
    const int nw = wid >> 2;       // n block (32 cols)

    float acc[2][4][4];
    #pragma unroll
    for (int i = 0; i < 2; i++)
        #pragma unroll
        for (int j = 0; j < 4; j++)
            #pragma unroll
            for (int q = 0; q < 4; q++) acc[i][j][q] = 0.f;

    // stage fill: A 1024 cp16 + B 512 cp16 = 1536 / 256 threads = 6 each
    auto prefetch = [&](int stage, int kc0) {
        uint32_t sdst = sb + stage * STAGE_BYTES;
        #pragma unroll
        for (int i = 0; i < 4; i++) {
            int idx = tid + i * 256;           // 0..1023
            int row = idx >> 3;
            int ch  = idx & 7;
            cp16(sdst + sw_off(row, ch),
                 gA + (size_t)row * F_IN + kc0 + ch * 8);
        }
        #pragma unroll
        for (int i = 0; i < 2; i++) {
            int idx = tid + i * 256;           // 0..511
            int row = idx >> 3;                // 0..63
            int ch  = idx & 7;
            cp16(sdst + A_SUB + sw_off(row, ch),
                 gB + (size_t)row * F_IN + kc0 + ch * 8);
        }
        asm volatile("cp.async.commit_group;" ::: "memory");
    };

    // Prefetch the entire K range (4 chunks, one commit group each)
    prefetch(0, 0);
    prefetch(1, BK);
    prefetch(2, 2 * BK);
    prefetch(3, 3 * BK);

    const int a_row = mw * 32 + (lane & 7) + ((lane >> 3 & 1) << 3);
    const int a_chx = lane >> 4;
    const int b_row = nw * 32 + (lane & 7) + ((lane >> 4) << 3);
    const int b_chx = (lane >> 3) & 1;

    #pragma unroll
    for (int c = 0; c < 4; c++) {
        if (c == 0)      asm volatile("cp.async.wait_group 3;" ::: "memory");
        else if (c == 1) asm volatile("cp.async.wait_group 2;" ::: "memory");
        else if (c == 2) asm volatile("cp.async.wait_group 1;" ::: "memory");
        else             asm volatile("cp.async.wait_group 0;" ::: "memory");
        __syncthreads();

        const uint32_t stb = sb + c * STAGE_BYTES;
        #pragma unroll
        for (int ks = 0; ks < 4; ks++) {
            const int c0 = ks * 2;
            uint32_t a[2][4];
            #pragma unroll
            for (int mi = 0; mi < 2; mi++)
                ldm_x4(a[mi][0], a[mi][1], a[mi][2], a[mi][3],
                       stb + sw_off(a_row + mi * 16, c0 + a_chx));
            uint32_t b[4][2];
            #pragma unroll
            for (int j = 0; j < 2; j++) {
                uint32_t r0, r1, r2, r3;
                ldm_x4(r0, r1, r2, r3,
                       stb + A_SUB + sw_off(b_row + j * 16, c0 + b_chx));
                b[2 * j][0] = r0; b[2 * j][1] = r1;
                b[2 * j + 1][0] = r2; b[2 * j + 1][1] = r3;
            }
            #pragma unroll
            for (int mi = 0; mi < 2; mi++)
                #pragma unroll
                for (int ni = 0; ni < 4; ni++)
                    mma_f16(acc[mi][ni], a[mi], b[ni]);
        }
        // no trailing barrier: stages are never reused
    }

    // Epilogue: add bias; write fp16 h
    const int col0 = nw * 32 + 2 * (lane & 3);   // within 64-col half
    #pragma unroll
    for (int mi = 0; mi < 2; mi++) {
        const int rl = mw * 32 + mi * 16 + (lane >> 2);
        #pragma unroll
        for (int half = 0; half < 2; half++) {
            const int m = tile * BM + rl + half * 8;
            if (m >= MROWS) continue;
            const int bidx = m / NN;
            const int n = m - bidx * NN;
            __half* op16 = g_h16 + (size_t)n * NODE_STRIDE + bidx * (HH * FF)
                         + head * FF + nh * BN;
            const float* bp = bias + head * FF + nh * BN;
            #pragma unroll
            for (int ni = 0; ni < 4; ni++) {
                const int col = col0 + ni * 8;
                float ox = acc[mi][ni][half * 2 + 0] + bp[col];
                float oy = acc[mi][ni][half * 2 + 1] + bp[col + 1];
                *(__half2*)(op16 + col) = __floats2half2_rn(ox, oy);
            }
        }
    }
}

// ---------------------------------------------------------------------------
// Aggregation (one block per src node), fp16 gather, fp32 accum.
// ---------------------------------------------------------------------------
#define ACHUNK 128
__global__ __launch_bounds__(256) void agg_kernel(
    const int* __restrict__ dst,
    float* __restrict__ out)
{
    const int n = blockIdx.x;
    const int t = threadIdx.x;
    const int e0 = g_rowstart[n];
    const int e1 = g_rowstart[n + 1];

    const int base = t * 8;              // 2048 elems = 256 threads * 8
    const int hi = (base >> 7) & 3;
    const int b  = base >> 9;

    __shared__ int   s_dst[ACHUNK];
    __shared__ float s_w[HH][ACHUNK];
    __shared__ float s_den[HH];

    float acc[8];
    #pragma unroll
    for (int j = 0; j < 8; j++) acc[j] = 0.f;
    float den_local = 0.f;

    for (int cs = e0; cs < e1; cs += ACHUNK) {
        const int m = min(cs + ACHUNK, e1) - cs;
        if (t < m) {
            int e = cs + t;
            int d = dst[e];
            s_dst[t] = d;
            #pragma unroll
            for (int h = 0; h < HH; h++) {
                float s = g_ps[h * NN + n] + g_pd[h * NN + d];
                s = (s >= 0.f) ? s : 0.2f * s;
                s = fminf(fmaxf(s, -2.f), 2.f);
                s_w[h][t] = __expf(s);
            }
        }
        __syncthreads();

        if (t < HH) {
            float sm = 0.f;
            for (int e = 0; e < m; e++) sm += s_w[t][e];
            den_local += sm;
        }

        #pragma unroll 2
        for (int e = 0; e < m; e++) {
            float w = s_w[hi][e];
            uint4 v = *(const uint4*)(g_h16 + (size_t)s_dst[e] * NODE_STRIDE + base);
            float2 f0 = __half22float2(*reinterpret_cast<__half2*>(&v.x));
            float2 f1 = __half22float2(*reinterpret_cast<__half2*>(&v.y));
            float2 f2 = __half22float2(*reinterpret_cast<__half2*>(&v.z));
            float2 f3 = __half22float2(*reinterpret_cast<__half2*>(&v.w));
            acc[0] = fmaf(w, f0.x, acc[0]);
            acc[1] = fmaf(w, f0.y, acc[1]);
            acc[2] = fmaf(w, f1.x, acc[2]);
            acc[3] = fmaf(w, f1.y, acc[3]);
            acc[4] = fmaf(w, f2.x, acc[4]);
            acc[5] = fmaf(w, f2.y, acc[5]);
            acc[6] = fmaf(w, f3.x, acc[6]);
            acc[7] = fmaf(w, f3.y, acc[7]);
        }
        __syncthreads();
    }

    if (t < HH) s_den[t] = den_local;
    __syncthreads();

    float inv = (e1 > e0) ? (1.f / s_den[hi]) : 0.f;
    float* op = out + ((size_t)b * NN + n) * CCOLS + (base & (CCOLS - 1));
    float4 o0, o1;
    o0.x = acc[0] * inv; o0.y = acc[1] * inv; o0.z = acc[2] * inv; o0.w = acc[3] * inv;
    o1.x = acc[4] * inv; o1.y = acc[5] * inv; o1.z = acc[6] * inv; o1.w = acc[7] * inv;
    ((float4*)op)[0] = o0;
    ((float4*)op)[1] = o1;
}

// ---------------------------------------------------------------------------
// Launch
// ---------------------------------------------------------------------------
extern "C" void kernel_launch(void* const* d_in, const int* in_sizes, int n_in,
                              void* d_out, int out_size)
{
    const float* x     = (const float*)d_in[0];
    const float* Wmlp  = (const float*)d_in[1];
    const float* bmlp  = (const float*)d_in[2];
    const float* Wattn = (const float*)d_in[3];
    const int*   src   = (const int*)d_in[4];
    const int*   dst   = (const int*)d_in[5];
    float*       out   = (float*)d_out;

    (void)in_sizes; (void)n_in; (void)out_size;

    cudaFuncSetAttribute(gemm_mma, cudaFuncAttributeMaxDynamicSharedMemorySize, GEMM_SMEM);

    prep_all<<<PREP_BLOCKS, 256>>>(x, Wmlp, bmlp, Wattn, src);
    pvec_kernel<<<(NN + 7) / 8, 256>>>(x);

    gemm_mma<<<dim3(HH * 2, MTILES), 256, GEMM_SMEM>>>(bmlp);

    agg_kernel<<<NN, 256>>>(dst, out);
}